// round 8
// baseline (speedup 1.0000x reference)
#include <cuda_runtime.h>
#include <cstddef>
#include <cstdint>

// Problem constants
#define BATCH 2
#define TT    1024
#define DM    1024
#define NH    16
#define TD    5
#define DH    64
#define PCOLS (NH * TD)   // 80

// Scratch (no allocation allowed -> __device__ globals)
__device__ float g_P[BATCH * TT * PCOLS];    // sigmoid(x@Wp + bp), (B*T, 80)
__device__ float g_V[BATCH * TT * DM];       // x@Wv,  (B*T, 1024)
__device__ float g_CTX[BATCH * TT * DM];     // attn@V reassembled, (B*T, 1024)

// ---------------------------------------------------------------------------
// tf32 helpers
// ---------------------------------------------------------------------------
__device__ __forceinline__ uint32_t f2tf32(float x) {
    uint32_t r;
    asm("cvt.rna.tf32.f32 %0, %1;" : "=r"(r) : "f"(x));
    return r;
}

__device__ __forceinline__ void mma_tf32(float4& c, const uint32_t a[4],
                                         const uint32_t b[2]) {
    asm volatile(
        "mma.sync.aligned.m16n8k8.row.col.f32.tf32.tf32.f32 "
        "{%0,%1,%2,%3}, {%4,%5,%6,%7}, {%8,%9}, {%0,%1,%2,%3};"
        : "+f"(c.x), "+f"(c.y), "+f"(c.z), "+f"(c.w)
        : "r"(a[0]), "r"(a[1]), "r"(a[2]), "r"(a[3]), "r"(b[0]), "r"(b[1]));
}

// exp(x) for x in (0,1]: e^x = e^0.5 * Taylor6(x-0.5).  |err| ~1.6e-6.
// 7 FMA-pipe ops instead of MUFU (rt=8) -- removes the MUFU bottleneck.
__device__ __forceinline__ float exp01(float x) {
    const float t = x - 0.5f;
    float p = fmaf(t, 1.388888889e-3f, 8.333333333e-3f);  // 1/720, 1/120
    p = fmaf(p, t, 4.166666667e-2f);                      // 1/24
    p = fmaf(p, t, 1.666666667e-1f);                      // 1/6
    p = fmaf(p, t, 0.5f);
    p = fmaf(p, t, 1.0f);
    p = fmaf(p, t, 1.0f);
    return 1.6487212707f * p;                             // e^0.5
}

// ---------------------------------------------------------------------------
// tf32 tensor-core GEMM: C[*,N] = A[*,K] @ B[K,N] (+bias+sigmoid if SIG).
// 128x128 block tile, BK=16, 512 threads = 16 warps (4m x 4n), warp tile 32x32.
// m16n8k8 thread mapping: g = lane>>2, t = lane&3
//   A frags: A[m+g][k+t], A[m+g+8][k+t], A[m+g][k+t+4], A[m+g+8][k+t+4]
//   B frags: B[k+t][n+g], B[k+t+4][n+g]
//   C: (g,2t)=x (g,2t+1)=y (g+8,2t)=z (g+8,2t+1)=w
// smem row pad 8 (stride 136) -> conflict-free fragment gathers.
// ---------------------------------------------------------------------------
#define BKt 16
#define TPAD 136
#define TS_A(st, k, m) sA[((st) * BKt + (k)) * TPAD + (m)]
#define TS_B(st, k, n) sB[((st) * BKt + (k)) * TPAD + (n)]

template<int N, int K, bool SIG>
__device__ __forceinline__ void tgemm_body(const float* __restrict__ A,
                                           const float* __restrict__ B,
                                           const float* __restrict__ bias,
                                           float* __restrict__ C,
                                           int bm, int bn,
                                           uint32_t* sA, uint32_t* sB)
{
    const int tid  = threadIdx.x;          // 0..511
    const int lane = tid & 31;
    const int wid  = tid >> 5;             // 0..15
    const int g    = lane >> 2;
    const int t    = lane & 3;
    const int wm   = (wid >> 2) * 32;      // warp m offset (4 rows of warps)
    const int wn   = (wid & 3) * 32;       // warp n offset (4 cols of warps)

    // loader indices: one float4 per thread per tile
    const int ar = tid >> 2, ac = (tid & 3) * 4;   // A: 128 x 16
    const int br = tid >> 5, bc = (tid & 31) * 4;  // B: 16 x 128

    // ---- initial tile -> stage 0
    {
        float4 va = *(const float4*)(A + (size_t)(bm + ar) * K + ac);
        TS_A(0, ac + 0, ar) = f2tf32(va.x);
        TS_A(0, ac + 1, ar) = f2tf32(va.y);
        TS_A(0, ac + 2, ar) = f2tf32(va.z);
        TS_A(0, ac + 3, ar) = f2tf32(va.w);
        float4 vb = (bn + bc < N) ? *(const float4*)(B + (size_t)br * N + bn + bc)
                                  : make_float4(0.f, 0.f, 0.f, 0.f);
        TS_B(0, br, bc + 0) = f2tf32(vb.x);
        TS_B(0, br, bc + 1) = f2tf32(vb.y);
        TS_B(0, br, bc + 2) = f2tf32(vb.z);
        TS_B(0, br, bc + 3) = f2tf32(vb.w);
    }
    __syncthreads();

    float4 acc[2][4];
    #pragma unroll
    for (int mi = 0; mi < 2; mi++)
        #pragma unroll
        for (int ni = 0; ni < 4; ni++)
            acc[mi][ni] = make_float4(0.f, 0.f, 0.f, 0.f);

    float4 pa, pb;
    int cur = 0;
    for (int k0 = 0; k0 < K; k0 += BKt) {
        const bool more = (k0 + BKt) < K;
        if (more) {   // prefetch next tile into registers (raw fp32)
            pa = *(const float4*)(A + (size_t)(bm + ar) * K + k0 + BKt + ac);
            pb = (bn + bc < N)
               ? *(const float4*)(B + (size_t)(k0 + BKt + br) * N + bn + bc)
               : make_float4(0.f, 0.f, 0.f, 0.f);
        }
        // ---- compute on current stage: 2 k8 sub-steps
        #pragma unroll
        for (int s = 0; s < 2; s++) {
            const int kb = s * 8;
            uint32_t af[2][4], bf[4][2];
            #pragma unroll
            for (int mi = 0; mi < 2; mi++) {
                const int m0 = wm + mi * 16;
                af[mi][0] = TS_A(cur, kb + t,     m0 + g);
                af[mi][1] = TS_A(cur, kb + t,     m0 + g + 8);
                af[mi][2] = TS_A(cur, kb + t + 4, m0 + g);
                af[mi][3] = TS_A(cur, kb + t + 4, m0 + g + 8);
            }
            #pragma unroll
            for (int ni = 0; ni < 4; ni++) {
                const int n0 = wn + ni * 8;
                bf[ni][0] = TS_B(cur, kb + t,     n0 + g);
                bf[ni][1] = TS_B(cur, kb + t + 4, n0 + g);
            }
            #pragma unroll
            for (int mi = 0; mi < 2; mi++)
                #pragma unroll
                for (int ni = 0; ni < 4; ni++)
                    mma_tf32(acc[mi][ni], af[mi], bf[ni]);
        }
        if (more) {   // commit prefetched tile to the other stage
            int nxt = cur ^ 1;
            TS_A(nxt, ac + 0, ar) = f2tf32(pa.x);
            TS_A(nxt, ac + 1, ar) = f2tf32(pa.y);
            TS_A(nxt, ac + 2, ar) = f2tf32(pa.z);
            TS_A(nxt, ac + 3, ar) = f2tf32(pa.w);
            TS_B(nxt, br, bc + 0) = f2tf32(pb.x);
            TS_B(nxt, br, bc + 1) = f2tf32(pb.y);
            TS_B(nxt, br, bc + 2) = f2tf32(pb.z);
            TS_B(nxt, br, bc + 3) = f2tf32(pb.w);
            __syncthreads();
            cur = nxt;
        }
    }

    // ---- epilogue from fragments (float2 stores)
    #pragma unroll
    for (int mi = 0; mi < 2; mi++) {
        const int r0 = bm + wm + mi * 16 + g;
        #pragma unroll
        for (int ni = 0; ni < 4; ni++) {
            const int col = bn + wn + ni * 8 + 2 * t;
            if (col < N) {
                float2 lo = make_float2(acc[mi][ni].x, acc[mi][ni].y);
                float2 hi = make_float2(acc[mi][ni].z, acc[mi][ni].w);
                if (SIG) {
                    lo.x = 1.f / (1.f + __expf(-(lo.x + bias[col + 0])));
                    lo.y = 1.f / (1.f + __expf(-(lo.y + bias[col + 1])));
                    hi.x = 1.f / (1.f + __expf(-(hi.x + bias[col + 0])));
                    hi.y = 1.f / (1.f + __expf(-(hi.y + bias[col + 1])));
                }
                *(float2*)(C + (size_t)r0 * N + col)       = lo;
                *(float2*)(C + (size_t)(r0 + 8) * N + col) = hi;
            }
        }
    }
}

// Fused V + P GEMM: blocks 0..127 do V = x@Wv, blocks 128..143 do
// P = sigmoid(x@Wp + bp). One wave on 148 SMs.
__global__ __launch_bounds__(512)
void gemm_vp_kernel(const float* __restrict__ x, const float* __restrict__ Wv,
                    const float* __restrict__ Wp, const float* __restrict__ bp)
{
    __shared__ uint32_t sA[2 * BKt * TPAD];
    __shared__ uint32_t sB[2 * BKt * TPAD];
    const int bid = blockIdx.x;
    if (bid < 128)
        tgemm_body<DM, DM, false>(x, Wv, nullptr, g_V,
                                  (bid >> 3) * 128, (bid & 7) * 128, sA, sB);
    else
        tgemm_body<PCOLS, DM, true>(x, Wp, bp, g_P,
                                    (bid - 128) * 128, 0, sA, sB);
}

__global__ __launch_bounds__(512)
void gemm_o_kernel(const float* __restrict__ Wo, float* __restrict__ out)
{
    __shared__ uint32_t sA[2 * BKt * TPAD];
    __shared__ uint32_t sB[2 * BKt * TPAD];
    tgemm_body<DM, DM, false>(g_CTX, Wo, nullptr, out,
                              blockIdx.y * 128, blockIdx.x * 128, sA, sB);
}

// ---------------------------------------------------------------------------
// Attention: per (b,h, 64-query block), 256 threads, ~19.7KB smem.
// Phase 1: 64x64 exp-sim computed once into smem (poly exp on FMA pipe),
//          TRANSPOSED EsT[k][q].
// Phase 2: 2-way k-split; thread tile = 2 queries x 16 dims; V rows read by
// LDG (L1-resident). k-split partials reduced once per block at the end.
// sim in (0,1] -> exp without max-subtraction is safe. Masked entries are 0.
// ---------------------------------------------------------------------------
#define EST_STRIDE 66
#define RED_STRIDE 36

__global__ __launch_bounds__(256)
void attn_kernel()
{
    __shared__ float kpT[TD][64];          // transposed key paths
    __shared__ float buf[128 * RED_STRIDE]; // EsT[64][66] (4224 fl) / red[128][36]

    const int bh = blockIdx.y;
    const int b  = bh >> 4;
    const int h  = bh & 15;
    const int qb = gridDim.x - 1 - blockIdx.x;   // heavy blocks first
    const int tid = threadIdx.x;

    // phase-1 mapping: q1 = query, kg = 16-key group
    const int q1 = tid & 63;
    const int kg = tid >> 6;
    const int qg1 = qb * 64 + q1;
    // phase-2 mapping: ks = k half, qg = 2-query group, ds = 16-dim split
    const int ks   = tid >> 7;         // 0..1
    const int slot = tid & 127;
    const int qg   = slot >> 2;        // 0..31
    const int ds   = slot & 3;         // 0..3

    // query path params for phase 1: agree = fma(2p-1, pk, 1-p)
    float uq[TD], vq[TD];
    {
        const float* prow = g_P + (size_t)(b * TT + qg1) * PCOLS + h * TD;
        #pragma unroll
        for (int d = 0; d < TD; d++) {
            float p = prow[d];
            uq[d] = 2.f * p - 1.f;
            vq[d] = 1.f - p;
        }
    }

    float4 accA[4], accB[4];
    #pragma unroll
    for (int i = 0; i < 4; i++) {
        accA[i] = make_float4(0.f, 0.f, 0.f, 0.f);
        accB[i] = make_float4(0.f, 0.f, 0.f, 0.f);
    }
    float denA = 0.f, denB = 0.f;

    for (int kb = 0; kb <= qb; kb++) {
        const int k0 = kb * 64;

        // stage key paths transposed (5 x 64)
        for (int i = tid; i < TD * 64; i += 256) {
            int d = i >> 6, k = i & 63;
            kpT[d][k] = g_P[(size_t)(b * TT + k0 + k) * PCOLS + h * TD + d];
        }
        __syncthreads();

        // phase 1: each thread computes 16 (q,k) pairs once -> EsT[k][q]
        #pragma unroll
        for (int j = 0; j < 16; j++) {
            const int k = kg * 16 + j;
            float cp = 1.f, s = 0.f;
            #pragma unroll
            for (int d = 0; d < TD; d++) {
                float a = fmaf(uq[d], kpT[d][k], vq[d]);
                cp *= a;
                s  += cp;
            }
            float e = exp01(s * 0.2f);
            if (k0 + k > qg1) e = 0.f;          // causal mask
            buf[k * EST_STRIDE + q1] = e;
        }
        __syncthreads();

        // phase 2: this thread's k half, 2 queries x 16 dims, V via LDG
        const float* vbase = g_V + (size_t)(b * TT + k0 + ks * 32) * DM
                             + h * DH + ds * 16;
        #pragma unroll 4
        for (int kk2 = 0; kk2 < 32; kk2++) {
            const int kk = ks * 32 + kk2;
            const float2 e2 = *(const float2*)&buf[kk * EST_STRIDE + qg * 2];
            const float4* vr = (const float4*)(vbase + (size_t)kk2 * DM);
            float4 v0 = vr[0], v1 = vr[1], v2 = vr[2], v3 = vr[3];
            denA += e2.x; denB += e2.y;
            accA[0].x = fmaf(e2.x, v0.x, accA[0].x); accA[0].y = fmaf(e2.x, v0.y, accA[0].y);
            accA[0].z = fmaf(e2.x, v0.z, accA[0].z); accA[0].w = fmaf(e2.x, v0.w, accA[0].w);
            accA[1].x = fmaf(e2.x, v1.x, accA[1].x); accA[1].y = fmaf(e2.x, v1.y, accA[1].y);
            accA[1].z = fmaf(e2.x, v1.z, accA[1].z); accA[1].w = fmaf(e2.x, v1.w, accA[1].w);
            accA[2].x = fmaf(e2.x, v2.x, accA[2].x); accA[2].y = fmaf(e2.x, v2.y, accA[2].y);
            accA[2].z = fmaf(e2.x, v2.z, accA[2].z); accA[2].w = fmaf(e2.x, v2.w, accA[2].w);
            accA[3].x = fmaf(e2.x, v3.x, accA[3].x); accA[3].y = fmaf(e2.x, v3.y, accA[3].y);
            accA[3].z = fmaf(e2.x, v3.z, accA[3].z); accA[3].w = fmaf(e2.x, v3.w, accA[3].w);
            accB[0].x = fmaf(e2.y, v0.x, accB[0].x); accB[0].y = fmaf(e2.y, v0.y, accB[0].y);
            accB[0].z = fmaf(e2.y, v0.z, accB[0].z); accB[0].w = fmaf(e2.y, v0.w, accB[0].w);
            accB[1].x = fmaf(e2.y, v1.x, accB[1].x); accB[1].y = fmaf(e2.y, v1.y, accB[1].y);
            accB[1].z = fmaf(e2.y, v1.z, accB[1].z); accB[1].w = fmaf(e2.y, v1.w, accB[1].w);
            accB[2].x = fmaf(e2.y, v2.x, accB[2].x); accB[2].y = fmaf(e2.y, v2.y, accB[2].y);
            accB[2].z = fmaf(e2.y, v2.z, accB[2].z); accB[2].w = fmaf(e2.y, v2.w, accB[2].w);
            accB[3].x = fmaf(e2.y, v3.x, accB[3].x); accB[3].y = fmaf(e2.y, v3.y, accB[3].y);
            accB[3].z = fmaf(e2.y, v3.z, accB[3].z); accB[3].w = fmaf(e2.y, v3.w, accB[3].w);
        }
        __syncthreads();   // EsT consumed; safe for next tile (or reduction)
    }

    // ---- k-split reduction (once per block), reusing buf as scratch
    if (ks == 1) {
        float4* r = (float4*)&buf[slot * RED_STRIDE];
        r[0] = accA[0]; r[1] = accA[1]; r[2] = accA[2]; r[3] = accA[3];
        r[4] = accB[0]; r[5] = accB[1]; r[6] = accB[2]; r[7] = accB[3];
        buf[slot * RED_STRIDE + 32] = denA;
        buf[slot * RED_STRIDE + 33] = denB;
    }
    __syncthreads();
    if (ks == 0) {
        const float4* r = (const float4*)&buf[slot * RED_STRIDE];
        #pragma unroll
        for (int i = 0; i < 4; i++) {
            float4 ra = r[i], rb2 = r[4 + i];
            accA[i].x += ra.x;  accA[i].y += ra.y;  accA[i].z += ra.z;  accA[i].w += ra.w;
            accB[i].x += rb2.x; accB[i].y += rb2.y; accB[i].z += rb2.z; accB[i].w += rb2.w;
        }
        denA += buf[slot * RED_STRIDE + 32];
        denB += buf[slot * RED_STRIDE + 33];

        const float invA = 1.f / denA;
        const float invB = 1.f / denB;
        const int q = qb * 64 + qg * 2;
        float4* o0 = (float4*)(g_CTX + (size_t)(b * TT + q) * DM + h * DH + ds * 16);
        float4* o1 = (float4*)(g_CTX + (size_t)(b * TT + q + 1) * DM + h * DH + ds * 16);
        #pragma unroll
        for (int i = 0; i < 4; i++) {
            o0[i] = make_float4(accA[i].x * invA, accA[i].y * invA,
                                accA[i].z * invA, accA[i].w * invA);
            o1[i] = make_float4(accB[i].x * invB, accB[i].y * invB,
                                accB[i].z * invB, accB[i].w * invB);
        }
    }
}

// ---------------------------------------------------------------------------
// Launch
// ---------------------------------------------------------------------------
extern "C" void kernel_launch(void* const* d_in, const int* in_sizes, int n_in,
                              void* d_out, int out_size)
{
    const float* x  = (const float*)d_in[0];
    const float* Wp = (const float*)d_in[1];
    const float* bp = (const float*)d_in[2];
    const float* Wv = (const float*)d_in[3];
    const float* Wo = (const float*)d_in[4];
    float* out = (float*)d_out;

    // V = x@Wv (128 blocks) fused with P = sigmoid(x@Wp+bp) (16 blocks)
    gemm_vp_kernel<<<144, 512>>>(x, Wv, Wp, bp);

    // attention -> CTX
    attn_kernel<<<dim3(TT / 64, BATCH * NH), 256>>>();

    // out = CTX @ Wo
    gemm_o_kernel<<<dim3(DM / 128, (BATCH * TT) / 128), 512>>>(Wo, out);
}

// round 11
// speedup vs baseline: 1.4985x; 1.4985x over previous
#include <cuda_runtime.h>
#include <cstddef>
#include <cstdint>

// Problem constants
#define BATCH 2
#define TT    1024
#define DM    1024
#define NH    16
#define TD    5
#define DH    64
#define PCOLS (NH * TD)   // 80

// Scratch (no allocation allowed -> __device__ globals)
__device__ float g_P[BATCH * TT * PCOLS];    // sigmoid(x@Wp + bp), (B*T, 80)
__device__ float g_V[BATCH * TT * DM];       // x@Wv,  (B*T, 1024)
__device__ float g_CTX[BATCH * TT * DM];     // attn@V reassembled, (B*T, 1024)

// ---------------------------------------------------------------------------
// tf32 helpers
// ---------------------------------------------------------------------------
__device__ __forceinline__ uint32_t f2tf32(float x) {
    uint32_t r;
    asm("cvt.rna.tf32.f32 %0, %1;" : "=r"(r) : "f"(x));
    return r;
}

__device__ __forceinline__ void mma_tf32(float4& c, const uint32_t a[4],
                                         const uint32_t b0, const uint32_t b1) {
    asm volatile(
        "mma.sync.aligned.m16n8k8.row.col.f32.tf32.tf32.f32 "
        "{%0,%1,%2,%3}, {%4,%5,%6,%7}, {%8,%9}, {%0,%1,%2,%3};"
        : "+f"(c.x), "+f"(c.y), "+f"(c.z), "+f"(c.w)
        : "r"(a[0]), "r"(a[1]), "r"(a[2]), "r"(a[3]), "r"(b0), "r"(b1));
}

// exp(x) for x in (0,1]: e^x = e^0.5 * Taylor6(x-0.5).  |err| ~1.6e-6.
__device__ __forceinline__ float exp01(float x) {
    const float t = x - 0.5f;
    float p = fmaf(t, 1.388888889e-3f, 8.333333333e-3f);
    p = fmaf(p, t, 4.166666667e-2f);
    p = fmaf(p, t, 1.666666667e-1f);
    p = fmaf(p, t, 0.5f);
    p = fmaf(p, t, 1.0f);
    p = fmaf(p, t, 1.0f);
    return 1.6487212707f * p;
}

// ---------------------------------------------------------------------------
// tf32 tensor-core GEMM (R7 validated config): C[*,N] = A[*,K] @ B[K,N].
// 128x128 block tile, BK=16, 256 threads = 8 warps (4m x 2n), warp tile 32x64.
// ---------------------------------------------------------------------------
#define BKt 16
#define TPAD 136
#define TS_A(st, k, m) sA[((st) * BKt + (k)) * TPAD + (m)]
#define TS_B(st, k, n) sB[((st) * BKt + (k)) * TPAD + (n)]

template<int N, int K, bool SIG>
__device__ __forceinline__ void tgemm_body(const float* __restrict__ A,
                                           const float* __restrict__ B,
                                           const float* __restrict__ bias,
                                           float* __restrict__ C,
                                           int bm, int bn,
                                           uint32_t* sA, uint32_t* sB)
{
    const int tid  = threadIdx.x;          // 0..255
    const int lane = tid & 31;
    const int wid  = tid >> 5;             // 0..7
    const int g    = lane >> 2;
    const int t    = lane & 3;
    const int wm   = (wid >> 1) * 32;
    const int wn   = (wid & 1) * 64;

    #define LD_TILE(st, koff)                                                  \
    {                                                                          \
        _Pragma("unroll")                                                      \
        for (int i = 0; i < 2; i++) {                                          \
            int f = tid + i * 256, r = f >> 2, c = (f & 3) * 4;                \
            float4 v = *(const float4*)(A + (size_t)(bm + r) * K + (koff) + c);\
            TS_A(st, c + 0, r) = f2tf32(v.x);                                  \
            TS_A(st, c + 1, r) = f2tf32(v.y);                                  \
            TS_A(st, c + 2, r) = f2tf32(v.z);                                  \
            TS_A(st, c + 3, r) = f2tf32(v.w);                                  \
        }                                                                      \
        _Pragma("unroll")                                                      \
        for (int i = 0; i < 2; i++) {                                          \
            int f = tid + i * 256, r = f >> 5, c = (f & 31) * 4;               \
            float4 v = (bn + c < N)                                            \
                ? *(const float4*)(B + (size_t)((koff) + r) * N + bn + c)      \
                : make_float4(0.f, 0.f, 0.f, 0.f);                             \
            TS_B(st, r, c + 0) = f2tf32(v.x);                                  \
            TS_B(st, r, c + 1) = f2tf32(v.y);                                  \
            TS_B(st, r, c + 2) = f2tf32(v.z);                                  \
            TS_B(st, r, c + 3) = f2tf32(v.w);                                  \
        }                                                                      \
    }

    LD_TILE(0, 0)
    __syncthreads();

    float4 acc[2][8];
    #pragma unroll
    for (int mi = 0; mi < 2; mi++)
        #pragma unroll
        for (int ni = 0; ni < 8; ni++)
            acc[mi][ni] = make_float4(0.f, 0.f, 0.f, 0.f);

    float4 pa[2], pb[2];
    int cur = 0;
    for (int k0 = 0; k0 < K; k0 += BKt) {
        const bool more = (k0 + BKt) < K;
        if (more) {
            #pragma unroll
            for (int i = 0; i < 2; i++) {
                int f = tid + i * 256, r = f >> 2, c = (f & 3) * 4;
                pa[i] = *(const float4*)(A + (size_t)(bm + r) * K + k0 + BKt + c);
            }
            #pragma unroll
            for (int i = 0; i < 2; i++) {
                int f = tid + i * 256, r = f >> 5, c = (f & 31) * 4;
                pb[i] = (bn + c < N)
                      ? *(const float4*)(B + (size_t)(k0 + BKt + r) * N + bn + c)
                      : make_float4(0.f, 0.f, 0.f, 0.f);
            }
        }
        #pragma unroll
        for (int s = 0; s < 2; s++) {
            const int kb = s * 8;
            uint32_t af[2][4], bf[8][2];
            #pragma unroll
            for (int mi = 0; mi < 2; mi++) {
                const int m0 = wm + mi * 16;
                af[mi][0] = TS_A(cur, kb + t,     m0 + g);
                af[mi][1] = TS_A(cur, kb + t,     m0 + g + 8);
                af[mi][2] = TS_A(cur, kb + t + 4, m0 + g);
                af[mi][3] = TS_A(cur, kb + t + 4, m0 + g + 8);
            }
            #pragma unroll
            for (int ni = 0; ni < 8; ni++) {
                const int n0 = wn + ni * 8;
                bf[ni][0] = TS_B(cur, kb + t,     n0 + g);
                bf[ni][1] = TS_B(cur, kb + t + 4, n0 + g);
            }
            #pragma unroll
            for (int mi = 0; mi < 2; mi++)
                #pragma unroll
                for (int ni = 0; ni < 8; ni++)
                    mma_tf32(acc[mi][ni], af[mi], bf[ni][0], bf[ni][1]);
        }
        if (more) {
            int nxt = cur ^ 1;
            #pragma unroll
            for (int i = 0; i < 2; i++) {
                int f = tid + i * 256, r = f >> 2, c = (f & 3) * 4;
                TS_A(nxt, c + 0, r) = f2tf32(pa[i].x);
                TS_A(nxt, c + 1, r) = f2tf32(pa[i].y);
                TS_A(nxt, c + 2, r) = f2tf32(pa[i].z);
                TS_A(nxt, c + 3, r) = f2tf32(pa[i].w);
            }
            #pragma unroll
            for (int i = 0; i < 2; i++) {
                int f = tid + i * 256, r = f >> 5, c = (f & 31) * 4;
                TS_B(nxt, r, c + 0) = f2tf32(pb[i].x);
                TS_B(nxt, r, c + 1) = f2tf32(pb[i].y);
                TS_B(nxt, r, c + 2) = f2tf32(pb[i].z);
                TS_B(nxt, r, c + 3) = f2tf32(pb[i].w);
            }
            __syncthreads();
            cur = nxt;
        }
    }

    #pragma unroll
    for (int mi = 0; mi < 2; mi++) {
        const int r0 = bm + wm + mi * 16 + g;
        #pragma unroll
        for (int ni = 0; ni < 8; ni++) {
            const int col = bn + wn + ni * 8 + 2 * t;
            if (col < N) {
                float2 lo = make_float2(acc[mi][ni].x, acc[mi][ni].y);
                float2 hi = make_float2(acc[mi][ni].z, acc[mi][ni].w);
                if (SIG) {
                    lo.x = 1.f / (1.f + __expf(-(lo.x + bias[col + 0])));
                    lo.y = 1.f / (1.f + __expf(-(lo.y + bias[col + 1])));
                    hi.x = 1.f / (1.f + __expf(-(hi.x + bias[col + 0])));
                    hi.y = 1.f / (1.f + __expf(-(hi.y + bias[col + 1])));
                }
                *(float2*)(C + (size_t)r0 * N + col)       = lo;
                *(float2*)(C + (size_t)(r0 + 8) * N + col) = hi;
            }
        }
    }
    #undef LD_TILE
}

__global__ __launch_bounds__(256)
void gemm_vp_kernel(const float* __restrict__ x, const float* __restrict__ Wv,
                    const float* __restrict__ Wp, const float* __restrict__ bp)
{
    __shared__ uint32_t sA[2 * BKt * TPAD];
    __shared__ uint32_t sB[2 * BKt * TPAD];
    const int bid = blockIdx.x;
    if (bid < 128)
        tgemm_body<DM, DM, false>(x, Wv, nullptr, g_V,
                                  (bid >> 3) * 128, (bid & 7) * 128, sA, sB);
    else
        tgemm_body<PCOLS, DM, true>(x, Wp, bp, g_P,
                                    (bid - 128) * 128, 0, sA, sB);
}

__global__ __launch_bounds__(256)
void gemm_o_kernel(const float* __restrict__ Wo, float* __restrict__ out)
{
    __shared__ uint32_t sA[2 * BKt * TPAD];
    __shared__ uint32_t sB[2 * BKt * TPAD];
    tgemm_body<DM, DM, false>(g_CTX, Wo, nullptr, out,
                              blockIdx.y * 128, blockIdx.x * 128, sA, sB);
}

// ---------------------------------------------------------------------------
// Attention with tensor-core PV. Per (b,h, 64-query block), 256 thr / 8 warps.
// Per key tile:
//   stage kpT (5x64) + V tile (64x64 fp32, stride 72)
//   phase 1: Es[q][k] = tf32(exp(sim)) once per pair (thread = (q, k-quarter));
//            per-thread denominator partial kept in a REGISTER across tiles.
//   phase 2: warp MMA  Es[64x64] @ (Vhi+Vlo)[64x64], V split to tf32 hi/lo in
//            registers (exact V), accumulators persist across tiles.
// sim in (0,1] -> no max subtraction needed; masked entries are exactly 0.
// ---------------------------------------------------------------------------
#define ES_STRIDE 68
#define VT_STRIDE 72

__global__ __launch_bounds__(256)
void attn_kernel()
{
    __shared__ uint32_t Es[64 * ES_STRIDE];   // exp-sim, tf32, row-major [q][k]
    __shared__ float    Vt[64 * VT_STRIDE];   // V tile fp32 [k][d]
    __shared__ float    kpT[TD][64];          // transposed key paths
    __shared__ float    den4[64][4];          // per-row denom partials

    const int bh = blockIdx.y;
    const int b  = bh >> 4;
    const int h  = bh & 15;
    const int qb = gridDim.x - 1 - blockIdx.x;   // heavy blocks first
    const int tid = threadIdx.x;
    const int lane = tid & 31;
    const int wid  = tid >> 5;
    const int g    = lane >> 2;
    const int t    = lane & 3;

    // phase-1 mapping: q1 = query row, kt = 16-key quarter
    const int q1 = tid >> 2;
    const int kt = tid & 3;
    const int qg1 = qb * 64 + q1;
    // phase-2 warp tile: rows wm4 + {g, g+8}, cols nb + ni*8 + 2t
    const int wm4 = (wid >> 1) * 16;
    const int nb  = (wid & 1) * 32;

    // query path params: agree = fma(2p-1, pk, 1-p)
    float uq[TD], vq[TD];
    {
        const float* prow = g_P + (size_t)(b * TT + qg1) * PCOLS + h * TD;
        #pragma unroll
        for (int d = 0; d < TD; d++) {
            float p = prow[d];
            uq[d] = 2.f * p - 1.f;
            vq[d] = 1.f - p;
        }
    }

    float4 acc[4];
    #pragma unroll
    for (int i = 0; i < 4; i++) acc[i] = make_float4(0.f, 0.f, 0.f, 0.f);
    float denLocal = 0.f;

    for (int kb = 0; kb <= qb; kb++) {
        const int k0 = kb * 64;

        // ---- stage key paths transposed (5 x 64)
        for (int i = tid; i < TD * 64; i += 256) {
            int d = i >> 6, k = i & 63;
            kpT[d][k] = g_P[(size_t)(b * TT + k0 + k) * PCOLS + h * TD + d];
        }
        // ---- stage V tile (64 x 64 fp32), coalesced float4
        #pragma unroll
        for (int i = 0; i < 4; i++) {
            int f = tid + i * 256;
            int r = f >> 4, c4 = f & 15;
            float4 v = *(const float4*)(g_V + (size_t)(b * TT + k0 + r) * DM
                                        + h * DH + c4 * 4);
            *(float4*)&Vt[r * VT_STRIDE + c4 * 4] = v;
        }
        __syncthreads();

        // ---- phase 1: 16 (q,k) pairs per thread -> Es[q][k] (tf32)
        #pragma unroll
        for (int j = 0; j < 16; j++) {
            const int k = kt * 16 + j;
            float cp = 1.f, s = 0.f;
            #pragma unroll
            for (int d = 0; d < TD; d++) {
                float a = fmaf(uq[d], kpT[d][k], vq[d]);
                cp *= a;
                s  += cp;
            }
            float e = exp01(s * 0.2f);
            if (k0 + k > qg1) e = 0.f;          // causal mask
            uint32_t ehat = f2tf32(e);
            Es[q1 * ES_STRIDE + k] = ehat;
            denLocal += __uint_as_float(ehat);  // denom consistent with MMA
        }
        __syncthreads();

        // ---- phase 2: warp MMA  Es @ V  (V split hi/lo for exactness)
        #pragma unroll
        for (int s = 0; s < 8; s++) {
            const int kk = s * 8;
            uint32_t af[4];
            af[0] = Es[(wm4 + g)     * ES_STRIDE + kk + t];
            af[1] = Es[(wm4 + g + 8) * ES_STRIDE + kk + t];
            af[2] = Es[(wm4 + g)     * ES_STRIDE + kk + t + 4];
            af[3] = Es[(wm4 + g + 8) * ES_STRIDE + kk + t + 4];
            #pragma unroll
            for (int ni = 0; ni < 4; ni++) {
                const int n0 = nb + ni * 8;
                float v0 = Vt[(kk + t)     * VT_STRIDE + n0 + g];
                float v1 = Vt[(kk + t + 4) * VT_STRIDE + n0 + g];
                uint32_t h0 = f2tf32(v0), h1 = f2tf32(v1);
                uint32_t l0 = f2tf32(v0 - __uint_as_float(h0));
                uint32_t l1 = f2tf32(v1 - __uint_as_float(h1));
                mma_tf32(acc[ni], af, h0, h1);
                mma_tf32(acc[ni], af, l0, l1);
            }
        }
        __syncthreads();   // Es/Vt consumed; safe to overwrite next tile
    }

    // ---- denominator assembly + epilogue
    den4[q1][kt] = denLocal;
    __syncthreads();

    const int r0 = wm4 + g;
    const int r1 = r0 + 8;
    float4 d0 = *(const float4*)&den4[r0][0];
    float4 d1 = *(const float4*)&den4[r1][0];
    const float inv0 = 1.f / (d0.x + d0.y + d0.z + d0.w);
    const float inv1 = 1.f / (d1.x + d1.y + d1.z + d1.w);

    float* out0 = g_CTX + (size_t)(b * TT + qb * 64 + r0) * DM + h * DH;
    float* out1 = g_CTX + (size_t)(b * TT + qb * 64 + r1) * DM + h * DH;
    #pragma unroll
    for (int ni = 0; ni < 4; ni++) {
        const int col = nb + ni * 8 + 2 * t;
        *(float2*)(out0 + col) = make_float2(acc[ni].x * inv0, acc[ni].y * inv0);
        *(float2*)(out1 + col) = make_float2(acc[ni].z * inv1, acc[ni].w * inv1);
    }
}

// ---------------------------------------------------------------------------
// Launch
// ---------------------------------------------------------------------------
extern "C" void kernel_launch(void* const* d_in, const int* in_sizes, int n_in,
                              void* d_out, int out_size)
{
    const float* x  = (const float*)d_in[0];
    const float* Wp = (const float*)d_in[1];
    const float* bp = (const float*)d_in[2];
    const float* Wv = (const float*)d_in[3];
    const float* Wo = (const float*)d_in[4];
    float* out = (float*)d_out;

    // V = x@Wv (128 blocks) fused with P = sigmoid(x@Wp+bp) (16 blocks)
    gemm_vp_kernel<<<144, 256>>>(x, Wv, Wp, bp);

    // attention -> CTX (tensor-core PV)
    attn_kernel<<<dim3(TT / 64, BATCH * NH), 256>>>();

    // out = CTX @ Wo
    gemm_o_kernel<<<dim3(DM / 128, (BATCH * TT) / 128), 256>>>(Wo, out);
}

// round 14
// speedup vs baseline: 1.9707x; 1.3152x over previous
#include <cuda_runtime.h>
#include <cstddef>
#include <cstdint>

// Problem constants
#define BATCH 2
#define TT    1024
#define DM    1024
#define NH    16
#define TD    5
#define DH    64
#define PCOLS (NH * TD)   // 80

// Scratch (no allocation allowed -> __device__ globals)
__device__ float g_P[BATCH * TT * PCOLS];    // sigmoid(x@Wp + bp), (B*T, 80)
__device__ float g_V[BATCH * TT * DM];       // x@Wv,  (B*T, 1024)
__device__ float g_CTX[BATCH * TT * DM];     // attn@V reassembled, (B*T, 1024)

// ---------------------------------------------------------------------------
// tf32 helpers
// ---------------------------------------------------------------------------
__device__ __forceinline__ uint32_t f2tf32(float x) {
    uint32_t r;
    asm("cvt.rna.tf32.f32 %0, %1;" : "=r"(r) : "f"(x));
    return r;
}

__device__ __forceinline__ void mma_tf32(float4& c, const uint32_t a[4],
                                         const uint32_t b0, const uint32_t b1) {
    asm volatile(
        "mma.sync.aligned.m16n8k8.row.col.f32.tf32.tf32.f32 "
        "{%0,%1,%2,%3}, {%4,%5,%6,%7}, {%8,%9}, {%0,%1,%2,%3};"
        : "+f"(c.x), "+f"(c.y), "+f"(c.z), "+f"(c.w)
        : "r"(a[0]), "r"(a[1]), "r"(a[2]), "r"(a[3]), "r"(b0), "r"(b1));
}

// exp(x) for x in (0,1]: e^x = e^0.5 * Taylor6(x-0.5).  |err| ~1.6e-6.
__device__ __forceinline__ float exp01(float x) {
    const float t = x - 0.5f;
    float p = fmaf(t, 1.388888889e-3f, 8.333333333e-3f);
    p = fmaf(p, t, 4.166666667e-2f);
    p = fmaf(p, t, 1.666666667e-1f);
    p = fmaf(p, t, 0.5f);
    p = fmaf(p, t, 1.0f);
    p = fmaf(p, t, 1.0f);
    return 1.6487212707f * p;
}

// ---------------------------------------------------------------------------
// tf32 tensor-core GEMM (validated config): C[*,N] = A[*,K] @ B[K,N].
// 128x128 block tile, BK=16, 256 threads = 8 warps (4m x 2n), warp tile 32x64.
// ---------------------------------------------------------------------------
#define BKt 16
#define TPAD 136
#define TS_A(st, k, m) sA[((st) * BKt + (k)) * TPAD + (m)]
#define TS_B(st, k, n) sB[((st) * BKt + (k)) * TPAD + (n)]

template<int N, int K, bool SIG>
__device__ __forceinline__ void tgemm_body(const float* __restrict__ A,
                                           const float* __restrict__ B,
                                           const float* __restrict__ bias,
                                           float* __restrict__ C,
                                           int bm, int bn,
                                           uint32_t* sA, uint32_t* sB)
{
    const int tid  = threadIdx.x;          // 0..255
    const int lane = tid & 31;
    const int wid  = tid >> 5;             // 0..7
    const int g    = lane >> 2;
    const int t    = lane & 3;
    const int wm   = (wid >> 1) * 32;
    const int wn   = (wid & 1) * 64;

    #define LD_TILE(st, koff)                                                  \
    {                                                                          \
        _Pragma("unroll")                                                      \
        for (int i = 0; i < 2; i++) {                                          \
            int f = tid + i * 256, r = f >> 2, c = (f & 3) * 4;                \
            float4 v = *(const float4*)(A + (size_t)(bm + r) * K + (koff) + c);\
            TS_A(st, c + 0, r) = f2tf32(v.x);                                  \
            TS_A(st, c + 1, r) = f2tf32(v.y);                                  \
            TS_A(st, c + 2, r) = f2tf32(v.z);                                  \
            TS_A(st, c + 3, r) = f2tf32(v.w);                                  \
        }                                                                      \
        _Pragma("unroll")                                                      \
        for (int i = 0; i < 2; i++) {                                          \
            int f = tid + i * 256, r = f >> 5, c = (f & 31) * 4;               \
            float4 v = (bn + c < N)                                            \
                ? *(const float4*)(B + (size_t)((koff) + r) * N + bn + c)      \
                : make_float4(0.f, 0.f, 0.f, 0.f);                             \
            TS_B(st, r, c + 0) = f2tf32(v.x);                                  \
            TS_B(st, r, c + 1) = f2tf32(v.y);                                  \
            TS_B(st, r, c + 2) = f2tf32(v.z);                                  \
            TS_B(st, r, c + 3) = f2tf32(v.w);                                  \
        }                                                                      \
    }

    LD_TILE(0, 0)
    __syncthreads();

    float4 acc[2][8];
    #pragma unroll
    for (int mi = 0; mi < 2; mi++)
        #pragma unroll
        for (int ni = 0; ni < 8; ni++)
            acc[mi][ni] = make_float4(0.f, 0.f, 0.f, 0.f);

    float4 pa[2], pb[2];
    int cur = 0;
    for (int k0 = 0; k0 < K; k0 += BKt) {
        const bool more = (k0 + BKt) < K;
        if (more) {
            #pragma unroll
            for (int i = 0; i < 2; i++) {
                int f = tid + i * 256, r = f >> 2, c = (f & 3) * 4;
                pa[i] = *(const float4*)(A + (size_t)(bm + r) * K + k0 + BKt + c);
            }
            #pragma unroll
            for (int i = 0; i < 2; i++) {
                int f = tid + i * 256, r = f >> 5, c = (f & 31) * 4;
                pb[i] = (bn + c < N)
                      ? *(const float4*)(B + (size_t)(k0 + BKt + r) * N + bn + c)
                      : make_float4(0.f, 0.f, 0.f, 0.f);
            }
        }
        #pragma unroll
        for (int s = 0; s < 2; s++) {
            const int kb = s * 8;
            uint32_t af[2][4], bf[8][2];
            #pragma unroll
            for (int mi = 0; mi < 2; mi++) {
                const int m0 = wm + mi * 16;
                af[mi][0] = TS_A(cur, kb + t,     m0 + g);
                af[mi][1] = TS_A(cur, kb + t,     m0 + g + 8);
                af[mi][2] = TS_A(cur, kb + t + 4, m0 + g);
                af[mi][3] = TS_A(cur, kb + t + 4, m0 + g + 8);
            }
            #pragma unroll
            for (int ni = 0; ni < 8; ni++) {
                const int n0 = wn + ni * 8;
                bf[ni][0] = TS_B(cur, kb + t,     n0 + g);
                bf[ni][1] = TS_B(cur, kb + t + 4, n0 + g);
            }
            #pragma unroll
            for (int mi = 0; mi < 2; mi++)
                #pragma unroll
                for (int ni = 0; ni < 8; ni++)
                    mma_tf32(acc[mi][ni], af[mi], bf[ni][0], bf[ni][1]);
        }
        if (more) {
            int nxt = cur ^ 1;
            #pragma unroll
            for (int i = 0; i < 2; i++) {
                int f = tid + i * 256, r = f >> 2, c = (f & 3) * 4;
                TS_A(nxt, c + 0, r) = f2tf32(pa[i].x);
                TS_A(nxt, c + 1, r) = f2tf32(pa[i].y);
                TS_A(nxt, c + 2, r) = f2tf32(pa[i].z);
                TS_A(nxt, c + 3, r) = f2tf32(pa[i].w);
            }
            #pragma unroll
            for (int i = 0; i < 2; i++) {
                int f = tid + i * 256, r = f >> 5, c = (f & 31) * 4;
                TS_B(nxt, r, c + 0) = f2tf32(pb[i].x);
                TS_B(nxt, r, c + 1) = f2tf32(pb[i].y);
                TS_B(nxt, r, c + 2) = f2tf32(pb[i].z);
                TS_B(nxt, r, c + 3) = f2tf32(pb[i].w);
            }
            __syncthreads();
            cur = nxt;
        }
    }

    #pragma unroll
    for (int mi = 0; mi < 2; mi++) {
        const int r0 = bm + wm + mi * 16 + g;
        #pragma unroll
        for (int ni = 0; ni < 8; ni++) {
            const int col = bn + wn + ni * 8 + 2 * t;
            if (col < N) {
                float2 lo = make_float2(acc[mi][ni].x, acc[mi][ni].y);
                float2 hi = make_float2(acc[mi][ni].z, acc[mi][ni].w);
                if (SIG) {
                    lo.x = 1.f / (1.f + __expf(-(lo.x + bias[col + 0])));
                    lo.y = 1.f / (1.f + __expf(-(lo.y + bias[col + 1])));
                    hi.x = 1.f / (1.f + __expf(-(hi.x + bias[col + 0])));
                    hi.y = 1.f / (1.f + __expf(-(hi.y + bias[col + 1])));
                }
                *(float2*)(C + (size_t)r0 * N + col)       = lo;
                *(float2*)(C + (size_t)(r0 + 8) * N + col) = hi;
            }
        }
    }
    #undef LD_TILE
}

__global__ __launch_bounds__(256)
void gemm_vp_kernel(const float* __restrict__ x, const float* __restrict__ Wv,
                    const float* __restrict__ Wp, const float* __restrict__ bp)
{
    __shared__ uint32_t sA[2 * BKt * TPAD];
    __shared__ uint32_t sB[2 * BKt * TPAD];
    const int bid = blockIdx.x;
    if (bid < 128)
        tgemm_body<DM, DM, false>(x, Wv, nullptr, g_V,
                                  (bid >> 3) * 128, (bid & 7) * 128, sA, sB);
    else
        tgemm_body<PCOLS, DM, true>(x, Wp, bp, g_P,
                                    (bid - 128) * 128, 0, sA, sB);
}

__global__ __launch_bounds__(256)
void gemm_o_kernel(const float* __restrict__ Wo, float* __restrict__ out)
{
    __shared__ uint32_t sA[2 * BKt * TPAD];
    __shared__ uint32_t sB[2 * BKt * TPAD];
    tgemm_body<DM, DM, false>(g_CTX, Wo, nullptr, out,
                              blockIdx.y * 128, blockIdx.x * 128, sA, sB);
}

// ---------------------------------------------------------------------------
// Attention with tensor-core PV. Per (b,h, 64-query block), 256 thr / 8 warps.
//   - V tile stored in smem as tf32 (converted ONCE at staging; single MMA,
//     no per-warp hi/lo splitting).
//   - Next tile's V + key-paths prefetched into registers during compute,
//     committed after the phase-2 sync (hides L2 latency).
//   - phase 1: Es[q][k] = tf32(exp(sim)) once per (q,k); per-thread denom
//     partial in a register across tiles (consistent with MMA numerator).
//   - phase 2: warp MMA Es[64x64] @ Vt[64x64]; accumulators persist.
// sim in (0,1] -> no max subtraction needed; masked entries are exactly 0.
// ---------------------------------------------------------------------------
#define ES_STRIDE 68
#define VT_STRIDE 72

__global__ __launch_bounds__(256)
void attn_kernel()
{
    __shared__ uint32_t Es[64 * ES_STRIDE];   // exp-sim, tf32, row-major [q][k]
    __shared__ uint32_t Vt[64 * VT_STRIDE];   // V tile, tf32 [k][d]
    __shared__ float    kpT[TD][64];          // transposed key paths
    __shared__ float    den4[64][4];          // per-row denom partials

    const int bh = blockIdx.y;
    const int b  = bh >> 4;
    const int h  = bh & 15;
    const int qb = gridDim.x - 1 - blockIdx.x;   // heavy blocks first
    const int tid = threadIdx.x;
    const int lane = tid & 31;
    const int wid  = tid >> 5;
    const int g    = lane >> 2;
    const int t    = lane & 3;

    // phase-1 mapping: q1 = query row, kt = 16-key quarter
    const int q1 = tid >> 2;
    const int kt = tid & 3;
    const int qg1 = qb * 64 + q1;
    // phase-2 warp tile: rows wm4 + {g, g+8}, cols nb + ni*8 + 2t
    const int wm4 = (wid >> 1) * 16;
    const int nb  = (wid & 1) * 32;

    // loader indices
    const int vr0 = tid >> 4;          // V rows tid>>4 + i*16
    const int vc4 = tid & 15;          // V col group (float4)
    const int kd  = tid >> 6;          // kp dim 0..3 (first 256 elems)
    const int kkk = tid & 63;          // kp key

    // query path params: agree = fma(2p-1, pk, 1-p)
    float uq[TD], vq[TD];
    {
        const float* prow = g_P + (size_t)(b * TT + qg1) * PCOLS + h * TD;
        #pragma unroll
        for (int d = 0; d < TD; d++) {
            float p = prow[d];
            uq[d] = 2.f * p - 1.f;
            vq[d] = 1.f - p;
        }
    }

    float4 acc[4];
    #pragma unroll
    for (int i = 0; i < 4; i++) acc[i] = make_float4(0.f, 0.f, 0.f, 0.f);
    float denLocal = 0.f;

    // prefetch registers
    float4 pv[4];
    float  pk0 = 0.f, pk1 = 0.f;

    #define PREFETCH(k0_)                                                      \
    {                                                                          \
        _Pragma("unroll")                                                      \
        for (int i = 0; i < 4; i++) {                                          \
            pv[i] = *(const float4*)(g_V + (size_t)(b * TT + (k0_) + vr0 +     \
                                     i * 16) * DM + h * DH + vc4 * 4);         \
        }                                                                      \
        pk0 = g_P[(size_t)(b * TT + (k0_) + kkk) * PCOLS + h * TD + kd];       \
        if (tid < 64)                                                          \
            pk1 = g_P[(size_t)(b * TT + (k0_) + tid) * PCOLS + h * TD + 4];    \
    }

    #define COMMIT()                                                           \
    {                                                                          \
        _Pragma("unroll")                                                      \
        for (int i = 0; i < 4; i++) {                                          \
            uint32_t* dst = &Vt[(vr0 + i * 16) * VT_STRIDE + vc4 * 4];         \
            dst[0] = f2tf32(pv[i].x); dst[1] = f2tf32(pv[i].y);                \
            dst[2] = f2tf32(pv[i].z); dst[3] = f2tf32(pv[i].w);                \
        }                                                                      \
        kpT[kd][kkk] = pk0;                                                    \
        if (tid < 64) kpT[4][tid] = pk1;                                       \
    }

    PREFETCH(0)
    COMMIT()
    __syncthreads();

    for (int kb = 0; kb <= qb; kb++) {
        const int k0 = kb * 64;

        // ---- phase 1: 16 (q,k) pairs per thread -> Es[q][k] (tf32)
        #pragma unroll
        for (int j = 0; j < 16; j++) {
            const int k = kt * 16 + j;
            float cp = 1.f, s = 0.f;
            #pragma unroll
            for (int d = 0; d < TD; d++) {
                float a = fmaf(uq[d], kpT[d][k], vq[d]);
                cp *= a;
                s  += cp;
            }
            float e = exp01(s * 0.2f);
            if (k0 + k > qg1) e = 0.f;          // causal mask
            uint32_t ehat = f2tf32(e);
            Es[q1 * ES_STRIDE + k] = ehat;
            denLocal += __uint_as_float(ehat);  // denom consistent with MMA
        }
        // issue next tile's global loads; they complete under phase 2
        if (kb < qb) PREFETCH(k0 + 64)
        __syncthreads();

        // ---- phase 2: warp MMA  Es @ Vt (both tf32 in smem)
        #pragma unroll
        for (int s = 0; s < 8; s++) {
            const int kk = s * 8;
            uint32_t af[4];
            af[0] = Es[(wm4 + g)     * ES_STRIDE + kk + t];
            af[1] = Es[(wm4 + g + 8) * ES_STRIDE + kk + t];
            af[2] = Es[(wm4 + g)     * ES_STRIDE + kk + t + 4];
            af[3] = Es[(wm4 + g + 8) * ES_STRIDE + kk + t + 4];
            #pragma unroll
            for (int ni = 0; ni < 4; ni++) {
                const int n0 = nb + ni * 8;
                mma_tf32(acc[ni], af,
                         Vt[(kk + t)     * VT_STRIDE + n0 + g],
                         Vt[(kk + t + 4) * VT_STRIDE + n0 + g]);
            }
        }
        __syncthreads();   // Es/Vt consumed

        if (kb < qb) {
            COMMIT()
            __syncthreads();   // kpT/Vt ready for next phase 1 / phase 2
        }
    }

    // ---- denominator assembly + epilogue
    den4[q1][kt] = denLocal;
    __syncthreads();

    const int r0 = wm4 + g;
    const int r1 = r0 + 8;
    float4 d0 = *(const float4*)&den4[r0][0];
    float4 d1 = *(const float4*)&den4[r1][0];
    const float inv0 = 1.f / (d0.x + d0.y + d0.z + d0.w);
    const float inv1 = 1.f / (d1.x + d1.y + d1.z + d1.w);

    float* out0 = g_CTX + (size_t)(b * TT + qb * 64 + r0) * DM + h * DH;
    float* out1 = g_CTX + (size_t)(b * TT + qb * 64 + r1) * DM + h * DH;
    #pragma unroll
    for (int ni = 0; ni < 4; ni++) {
        const int col = nb + ni * 8 + 2 * t;
        *(float2*)(out0 + col) = make_float2(acc[ni].x * inv0, acc[ni].y * inv0);
        *(float2*)(out1 + col) = make_float2(acc[ni].z * inv1, acc[ni].w * inv1);
    }
    #undef PREFETCH
    #undef COMMIT
}

// ---------------------------------------------------------------------------
// Launch
// ---------------------------------------------------------------------------
extern "C" void kernel_launch(void* const* d_in, const int* in_sizes, int n_in,
                              void* d_out, int out_size)
{
    const float* x  = (const float*)d_in[0];
    const float* Wp = (const float*)d_in[1];
    const float* bp = (const float*)d_in[2];
    const float* Wv = (const float*)d_in[3];
    const float* Wo = (const float*)d_in[4];
    float* out = (float*)d_out;

    // V = x@Wv (128 blocks) fused with P = sigmoid(x@Wp+bp) (16 blocks)
    gemm_vp_kernel<<<144, 256>>>(x, Wv, Wp, bp);

    // attention -> CTX (tensor-core PV, tf32 V, prefetch pipeline)
    attn_kernel<<<dim3(TT / 64, BATCH * NH), 256>>>();

    // out = CTX @ Wo
    gemm_o_kernel<<<dim3(DM / 128, (BATCH * TT) / 128), 256>>>(Wo, out);
}